// round 15
// baseline (speedup 1.0000x reference)
#include <cuda_runtime.h>
#include <math.h>

#define Bb      128
#define Ll      2048
#define NOBS    32
#define NHID    512
#define NSTEPS  (Ll - 1)          // 2047
#define NCTA    128
#define NTHREADS 128
typedef unsigned long long u64;
typedef unsigned int u32;
#define NBUMPS  ((u32)(NSTEPS - 1))   // 2046 bumps per warp per replay

// SMEM: A pre-duplicated [256 k2][16 q][4 u64] + per-warp X [2 pairs][514] u64
#define SAD_U64    (256 * 16 * 4)               // 16384 u64 = 131072 B
#define SXW_U64    (2 * 514)                    // per-warp X region (8224 B)
#define SMEM_BYTES ((SAD_U64 + 4 * SXW_U64) * 8)   // 163968 B

// per-(m-tile, warp, n-tile) producer flags; one 128B line per (mt,w)
__device__ __align__(128) u32 g_flags[8][4][32];

// ---------------------------------------------------------------------------
__device__ __forceinline__ u64 pack2(float a, float b) {
    u64 r;
    asm("mov.b64 %0, {%1, %2};" : "=l"(r) : "f"(a), "f"(b));
    return r;
}
__device__ __forceinline__ void unpack2(u64 v, float& a, float& b) {
    asm("mov.b64 {%0, %1}, %2;" : "=f"(a), "=f"(b) : "l"(v));
}
__device__ __forceinline__ void ffma2(u64& acc, u64 a, u64 x) {
    asm("fma.rn.f32x2 %0, %1, %2, %0;" : "+l"(acc) : "l"(a), "l"(x));
}
__device__ __forceinline__ u64 acq64(const u32* p) {
    u64 v;
    asm volatile("ld.global.acquire.gpu.u64 %0, [%1];" : "=l"(v) : "l"(p));
    return v;
}
__device__ __forceinline__ u32 acq32(const u32* p) {
    u32 v;
    asm volatile("ld.global.acquire.gpu.u32 %0, [%1];" : "=r"(v) : "l"(p));
    return v;
}
// spin until both u32 halves at f2 (8B-aligned) reach bt
__device__ __forceinline__ void wait2(const u32* f2, u32 bt) {
    u64 v = acq64(f2);
    while ((u32)v < bt || (u32)(v >> 32) < bt) v = acq64(f2);
}

// XLA EmitFastTanh (fma path) — verified bit-exact (rel_err 0.0). DO NOT CHANGE.
__device__ __forceinline__ float tanh_xla(float x) {
    const float kClamp = 7.99881172180175781f;
    float xc = fminf(fmaxf(x, -kClamp), kClamp);
    float x2 = __fmul_rn(xc, xc);
    float num = -2.76076847742355e-16f;
    num = fmaf(x2, num, 2.00018790482477e-13f);
    num = fmaf(x2, num, -8.60467152213735e-11f);
    num = fmaf(x2, num, 5.12229709037114e-08f);
    num = fmaf(x2, num, 1.48572235717979e-05f);
    num = fmaf(x2, num, 6.37261928875436e-04f);
    num = fmaf(x2, num, 4.89352455891786e-03f);
    num = __fmul_rn(xc, num);
    float den = 1.19825839466702e-06f;
    den = fmaf(x2, den, 1.18534705686654e-04f);
    den = fmaf(x2, den, 2.26843463243900e-03f);
    den = fmaf(x2, den, 4.89352518554385e-03f);
    float r = __fdiv_rn(num, den);
    return (fabsf(x) < 0.0004f) ? x : r;
}

// ---------------------------------------------------------------------------
// Persistent HCNN scan, order-exact fp32, warp-autonomous dataflow (R13)
// with A stored PRE-DUPLICATED in SMEM: inner loop = 3 LDS.128 + 4 FFMA2
// per k2, zero lane-duplication MOVs. Chain values/order identical to the
// bit-exact R13 kernel.
// ---------------------------------------------------------------------------
__global__ void __launch_bounds__(NTHREADS, 1) ptf_persistent(
    const float* __restrict__ data,   // [B, L, NOBS]
    const float* __restrict__ Amat,   // [NHID, NHID]
    const float* __restrict__ h0,     // [NHID]
    float* __restrict__ exps,
    float* __restrict__ states,       // doubles as the recurrent state
    float* __restrict__ deltas,
    float* __restrict__ partials)
{
    extern __shared__ u64 smem_u64[];
    u64* sAd   = smem_u64;                       // [256][16][4] (a,a) pairs
    u64* sxall = smem_u64 + SAD_U64;             // [4 warps][2][514]

    const int tid = threadIdx.x;
    const int w   = tid >> 5;
    const int l   = tid & 31;
    const int nt  = blockIdx.x & 15;
    const int mt  = blockIdx.x >> 4;
    const int n0  = nt * 32;
    const int m0  = mt * 16;

    const u32* flagrow = &g_flags[mt][w][0];
    u32* myflag = &g_flags[mt][w][nt];
    u32 base = acq32(myflag);
    base -= base % NBUMPS;                 // monotonic across graph replays

    // ---- one-time: A -> sAd[k2][q][4] = {(an,an)k, (an,an)k+1,
    //                                      (an1,an1)k, (an1,an1)k+1} ----
    for (int i = tid; i < 256 * 16; i += NTHREADS) {
        const int k2 = i >> 4;
        const int q  = i & 15;
        const int n  = n0 + 2 * q;
        float2 a0 = *(const float2*)&Amat[(size_t)n * NHID + 2 * k2];
        float2 a1 = *(const float2*)&Amat[(size_t)(n + 1) * NHID + 2 * k2];
        u64* d = &sAd[(size_t)i * 4];
        d[0] = pack2(a0.x, a0.x);
        d[1] = pack2(a0.y, a0.y);
        d[2] = pack2(a1.x, a1.x);
        d[3] = pack2(a1.y, a1.y);
    }
    __syncthreads();                       // only CTA-wide sync in the kernel

    // lane identifiers (staging and compute share the same mapping)
    const int p2 = l >> 4;                 // pair half 0/1
    const int q  = l & 15;                 // col-pair / k-quad index
    const int P  = 2 * w + p2;             // this lane's pair
    const int bA = m0 + P;                 // batches bA, bA+8
    const int bB = bA + 8;
    const int nA = n0 + 2 * q;             // compute cols nA, nA+1
    u64* xr = sxall + (size_t)w * SXW_U64 + (size_t)p2 * 514;

    for (int t = 0; t < NSTEPS; t++) {
        const u32 bt = base + (u32)t;

        // ---------- stage chunk 0 (k 0..63; includes injection/outputs) ------
        if (t > 0) wait2(flagrow, bt);     // producers nt=0,1
        {
            const int k0 = 4 * q;          // 0..60
            float4 fa, fb;
            if (t == 0) {
                fa = *(const float4*)(h0 + k0);
                fb = fa;
                if (nt == 0) {             // states[:,0,:] = s0 (pre-inject)
                    *(float4*)&states[((size_t)bA * Ll) * NHID + k0] = fa;
                    *(float4*)&states[((size_t)bB * Ll) * NHID + k0] = fb;
                }
            } else {
                fa = *(const float4*)&states[((size_t)bA * Ll + t) * NHID + k0];
                fb = *(const float4*)&states[((size_t)bB * Ll + t) * NHID + k0];
            }
            if (q < 8) {                   // k0 < 32: teacher forcing s + (y-s)
                float4 yA = *(const float4*)&data[((size_t)bA * Ll + t) * NOBS + k0];
                float4 yB = *(const float4*)&data[((size_t)bB * Ll + t) * NOBS + k0];
                float4 dA, dB;
                dA.x = __fsub_rn(yA.x, fa.x); dA.y = __fsub_rn(yA.y, fa.y);
                dA.z = __fsub_rn(yA.z, fa.z); dA.w = __fsub_rn(yA.w, fa.w);
                dB.x = __fsub_rn(yB.x, fb.x); dB.y = __fsub_rn(yB.y, fb.y);
                dB.z = __fsub_rn(yB.z, fb.z); dB.w = __fsub_rn(yB.w, fb.w);
                if (nt == 0) {
                    size_t oA = ((size_t)bA * Ll + t) * NOBS + k0;
                    size_t oB = ((size_t)bB * Ll + t) * NOBS + k0;
                    *(float4*)&exps[oA] = fa;  *(float4*)&exps[oB] = fb;
                    *(float4*)&deltas[oA]   = dA; *(float4*)&deltas[oB]   = dB;
                    *(float4*)&partials[oA] = dA; *(float4*)&partials[oB] = dB;
                }
                fa.x = __fadd_rn(fa.x, dA.x); fa.y = __fadd_rn(fa.y, dA.y);
                fa.z = __fadd_rn(fa.z, dA.z); fa.w = __fadd_rn(fa.w, dA.w);
                fb.x = __fadd_rn(fb.x, dB.x); fb.y = __fadd_rn(fb.y, dB.y);
                fb.z = __fadd_rn(fb.z, dB.z); fb.w = __fadd_rn(fb.w, dB.w);
            }
            u64* d = xr + k0;
            ulonglong2 lo, hi;
            lo.x = pack2(fa.x, fb.x); lo.y = pack2(fa.y, fb.y);
            hi.x = pack2(fa.z, fb.z); hi.y = pack2(fa.w, fb.w);
            *(ulonglong2*)(d)     = lo;
            *(ulonglong2*)(d + 2) = hi;
        }
        __syncwarp();

        // ---------- chunked compute, prefetch next chunk under FMA -----------
        u64 acc0 = 0, acc1 = 0;            // cols nA, nA+1 (both lanes 0.0f)
        #pragma unroll 1
        for (int c = 0; c < 8; c++) {
            float4 ga, gb;
            const bool more = (c < 7);
            if (more) {                    // poll + LDG chunk c+1 (hidden)
                if (t > 0) wait2(flagrow + 2 * (c + 1), bt);
                const int kn = 64 * (c + 1) + 4 * q;
                if (t == 0) {
                    ga = *(const float4*)(h0 + kn);
                    gb = ga;
                    if (nt == 0) {
                        *(float4*)&states[((size_t)bA * Ll) * NHID + kn] = ga;
                        *(float4*)&states[((size_t)bB * Ll) * NHID + kn] = gb;
                    }
                } else {
                    ga = *(const float4*)&states[((size_t)bA * Ll + t) * NHID + kn];
                    gb = *(const float4*)&states[((size_t)bB * Ll + t) * NHID + kn];
                }
            }

            // compute chunk c: k2 in [32c, 32c+32), ascending (bit-exact)
            const u64* xc = xr + 64 * c;
            const u64* ac = sAd + ((size_t)(32 * c * 16) + q) * 4;
            #pragma unroll
            for (int j = 0; j < 32; j++) {
                ulonglong2 X   = *(const ulonglong2*)(xc + 2 * j);
                const u64* ap  = ac + (size_t)j * 64;
                ulonglong2 Ad0 = *(const ulonglong2*)(ap);      // (an,an)k,k+1
                ulonglong2 Ad1 = *(const ulonglong2*)(ap + 2);  // (an1,an1)k,k+1
                ffma2(acc0, Ad0.x, X.x);   // col nA,   k
                ffma2(acc1, Ad1.x, X.x);   // col nA+1, k
                ffma2(acc0, Ad0.y, X.y);   // col nA,   k+1
                ffma2(acc1, Ad1.y, X.y);   // col nA+1, k+1
            }

            if (more) {                    // stage chunk c+1 (no injection: k>=64)
                u64* d = xr + 64 * (c + 1) + 4 * q;
                ulonglong2 lo, hi;
                lo.x = pack2(ga.x, gb.x); lo.y = pack2(ga.y, gb.y);
                hi.x = pack2(ga.z, gb.z); hi.y = pack2(ga.w, gb.w);
                *(ulonglong2*)(d)     = lo;
                *(ulonglong2*)(d + 2) = hi;
                __syncwarp();
            }
        }

        // ---------- tanh + writes -------------------------------------------
        float z0a, z0b, z1a, z1b;
        unpack2(acc0, z0a, z0b);           // (bA,nA), (bB,nA)
        unpack2(acc1, z1a, z1b);           // (bA,nA+1), (bB,nA+1)
        const float h00 = tanh_xla(z0a);
        const float h10 = tanh_xla(z1a);
        const float h01 = tanh_xla(z0b);
        const float h11 = tanh_xla(z1b);

        float* so = states + ((size_t)t + 1) * NHID + nA;
        *(float2*)(so + (size_t)bA * Ll * NHID) = make_float2(h00, h10);
        *(float2*)(so + (size_t)bB * Ll * NHID) = make_float2(h01, h11);

        if (t == NSTEPS - 1 && nt == 0) {  // nA, nA+1 < 32 here
            size_t oA = ((size_t)bA * Ll + (Ll - 1)) * NOBS + nA;
            size_t oB = ((size_t)bB * Ll + (Ll - 1)) * NOBS + nA;
            size_t dIA = ((size_t)bA * Ll + (Ll - 2)) * NOBS + nA;
            size_t dIB = ((size_t)bB * Ll + (Ll - 2)) * NOBS + nA;
            exps[oA] = h00; exps[oA + 1] = h10;
            exps[oB] = h01; exps[oB + 1] = h11;
            float dAx = __fsub_rn(data[dIA],     h00);
            float dAy = __fsub_rn(data[dIA + 1], h10);
            float dBx = __fsub_rn(data[dIB],     h01);
            float dBy = __fsub_rn(data[dIB + 1], h11);
            deltas[oA] = dAx; deltas[oA + 1] = dAy;
            deltas[oB] = dBx; deltas[oB + 1] = dBy;
            partials[oA] = dAx; partials[oA + 1] = dAy;
            partials[oB] = dBx; partials[oB + 1] = dBy;
        }

        // ---------- publish this warp's progress ----------------------------
        if (t < NSTEPS - 1) {
            __syncwarp();                  // order all lanes' STGs (warp fence)
            if (l == 0)
                asm volatile("red.global.release.gpu.add.u32 [%0], %1;"
                             :: "l"(myflag), "r"(1u) : "memory");
        }
    }
}

// ---------------------------------------------------------------------------
extern "C" void kernel_launch(void* const* d_in, const int* in_sizes, int n_in,
                              void* d_out, int out_size) {
    const float* data = (const float*)d_in[0];  // [128,2048,32]
    const float* A    = (const float*)d_in[1];  // [512,512]
    const float* h0   = (const float*)d_in[2];  // [1,512]
    // d_in[3] = prob (0) -> dropout identity

    float* out      = (float*)d_out;
    float* exps     = out;
    float* states   = exps   + (size_t)Bb * Ll * NOBS;
    float* deltas   = states + (size_t)Bb * Ll * NHID;
    float* partials = deltas + (size_t)Bb * Ll * NOBS;

    cudaFuncSetAttribute(ptf_persistent,
                         cudaFuncAttributeMaxDynamicSharedMemorySize, SMEM_BYTES);
    ptf_persistent<<<NCTA, NTHREADS, SMEM_BYTES>>>(data, A, h0,
                                                   exps, states, deltas, partials);
}

// round 16
// speedup vs baseline: 1.3232x; 1.3232x over previous
#include <cuda_runtime.h>
#include <math.h>

#define Bb      128
#define Ll      2048
#define NOBS    32
#define NHID    512
#define NSTEPS  (Ll - 1)          // 2047
#define NCTA    128
#define NTHREADS 128
typedef unsigned long long u64;
typedef unsigned int u32;
#define NBUMPS  ((u32)(NSTEPS - 1))   // 2046 bumps per warp per replay

// SMEM: only A interleaved [256 k2][16 q][4 floats]
#define SA2_FLOATS (256 * 16 * 4)               // 65536 B
#define SMEM_BYTES (SA2_FLOATS * 4)

// per-(m-tile, warp, n-tile) producer flags; one 128B line per (mt,w)
__device__ __align__(128) u32 g_flags[8][4][32];
// packed state ping-pong: [mt][pair][parity][col] = (vA,vB) u64  (512 KB)
__device__ __align__(128) u64 g_xpack[8][8][2][NHID];

// ---------------------------------------------------------------------------
__device__ __forceinline__ u64 pack2(float a, float b) {
    u64 r;
    asm("mov.b64 %0, {%1, %2};" : "=l"(r) : "f"(a), "f"(b));
    return r;
}
__device__ __forceinline__ void unpack2(u64 v, float& a, float& b) {
    asm("mov.b64 {%0, %1}, %2;" : "=f"(a), "=f"(b) : "l"(v));
}
__device__ __forceinline__ void ffma2(u64& acc, u64 a, u64 x) {
    asm("fma.rn.f32x2 %0, %1, %2, %0;" : "+l"(acc) : "l"(a), "l"(x));
}
__device__ __forceinline__ ulonglong2 ldcg2(const u64* p) {
    ulonglong2 v;
    asm volatile("ld.global.cg.v2.u64 {%0, %1}, [%2];"
                 : "=l"(v.x), "=l"(v.y) : "l"(p));
    return v;
}
__device__ __forceinline__ void stcg2(u64* p, u64 a, u64 b) {
    asm volatile("st.global.cg.v2.u64 [%0], {%1, %2};"
                 :: "l"(p), "l"(a), "l"(b) : "memory");
}
__device__ __forceinline__ u64 acq64(const u32* p) {
    u64 v;
    asm volatile("ld.global.acquire.gpu.u64 %0, [%1];" : "=l"(v) : "l"(p));
    return v;
}
__device__ __forceinline__ u32 acq32(const u32* p) {
    u32 v;
    asm volatile("ld.global.acquire.gpu.u32 %0, [%1];" : "=r"(v) : "l"(p));
    return v;
}
__device__ __forceinline__ void wait2(const u32* f2, u32 bt) {
    u64 v = acq64(f2);
    while ((u32)v < bt || (u32)(v >> 32) < bt) v = acq64(f2);
}

// XLA EmitFastTanh (fma path) — verified bit-exact (rel_err 0.0). DO NOT CHANGE.
__device__ __forceinline__ float tanh_xla(float x) {
    const float kClamp = 7.99881172180175781f;
    float xc = fminf(fmaxf(x, -kClamp), kClamp);
    float x2 = __fmul_rn(xc, xc);
    float num = -2.76076847742355e-16f;
    num = fmaf(x2, num, 2.00018790482477e-13f);
    num = fmaf(x2, num, -8.60467152213735e-11f);
    num = fmaf(x2, num, 5.12229709037114e-08f);
    num = fmaf(x2, num, 1.48572235717979e-05f);
    num = fmaf(x2, num, 6.37261928875436e-04f);
    num = fmaf(x2, num, 4.89352455891786e-03f);
    num = __fmul_rn(xc, num);
    float den = 1.19825839466702e-06f;
    den = fmaf(x2, den, 1.18534705686654e-04f);
    den = fmaf(x2, den, 2.26843463243900e-03f);
    den = fmaf(x2, den, 4.89352518554385e-03f);
    float r = __fdiv_rn(num, den);
    return (fabsf(x) < 0.0004f) ? x : r;
}

// 8-k2 block load (broadcast .cg LDG; 16 lanes/half share each address)
#define LOADB(buf_, blk_) do {                                        \
    const u64* _s = xp + 16 * (blk_);                                 \
    _Pragma("unroll")                                                 \
    for (int _j = 0; _j < 8; _j++) buf_[_j] = ldcg2(_s + 2 * _j);     \
} while (0)

// 8-k2 block FMA, ascending k (bit-exact R13 chain order)
#define FMAB(buf_, blk_) do {                                         \
    const float* _a = sA2 + ((size_t)(8 * (blk_)) * 16 + q) * 4;      \
    _Pragma("unroll")                                                 \
    for (int _j = 0; _j < 8; _j++) {                                  \
        float4 Aq = *(const float4*)(_a + (size_t)_j * 64);           \
        ffma2(acc0, pack2(Aq.x, Aq.x), buf_[_j].x);                   \
        ffma2(acc1, pack2(Aq.z, Aq.z), buf_[_j].x);                   \
        ffma2(acc0, pack2(Aq.y, Aq.y), buf_[_j].y);                   \
        ffma2(acc1, pack2(Aq.w, Aq.w), buf_[_j].y);                   \
    }                                                                 \
} while (0)

// wait for the producers of block blk_'s chunk (4 blocks per 64-col chunk)
#define MW(blk_) do {                                                 \
    if ((((blk_) & 3) == 0) && t > 0)                                 \
        wait2(flagrow + (((blk_) >> 2) * 2), bt);                     \
} while (0)

// ---------------------------------------------------------------------------
// Persistent HCNN scan, order-exact fp32, warp-autonomous, GLOBAL PACKED X.
// 128 CTAs = 16 n-tiles x 8 m-tiles; warp w owns pairs {2w,2w+1}.
// Producers store injected, pre-packed (vA,vB) u64 X to g_xpack (ping-pong
// parity); consumers fetch via broadcast .cg LDG.128 (coalescer dedups ->
// 2 wf/k2 vs 4 wf LDS), triple-buffered 8-k2 register pipeline. A in SMEM.
// ffma2 chain values + order identical to the bit-exact R13 kernel.
// ---------------------------------------------------------------------------
__global__ void __launch_bounds__(NTHREADS, 1) ptf_persistent(
    const float* __restrict__ data,   // [B, L, NOBS]
    const float* __restrict__ Amat,   // [NHID, NHID]
    const float* __restrict__ h0,     // [NHID]
    float* __restrict__ exps,
    float* __restrict__ states,       // full state history output
    float* __restrict__ deltas,
    float* __restrict__ partials)
{
    extern __shared__ float sA2[];    // [256][16][4]

    const int tid = threadIdx.x;
    const int w   = tid >> 5;
    const int l   = tid & 31;
    const int nt  = blockIdx.x & 15;
    const int mt  = blockIdx.x >> 4;
    const int n0  = nt * 32;
    const int m0  = mt * 16;

    const u32* flagrow = &g_flags[mt][w][0];
    u32* myflag = &g_flags[mt][w][nt];
    u32 base = acq32(myflag);
    base -= base % NBUMPS;                 // monotonic across graph replays

    // ---- one-time: A -> sA2[k2][q][4] ----
    for (int i = tid; i < 256 * 16; i += NTHREADS) {
        const int k2 = i >> 4;
        const int qq = i & 15;
        const int n  = n0 + 2 * qq;
        float2 a0 = *(const float2*)&Amat[(size_t)n * NHID + 2 * k2];
        float2 a1 = *(const float2*)&Amat[(size_t)(n + 1) * NHID + 2 * k2];
        *(float4*)&sA2[(size_t)i * 4] = make_float4(a0.x, a0.y, a1.x, a1.y);
    }

    // ---- init: fill parity-0 x-pack (s0 = h0, injected with y_0), t'=0 outputs
    {
        const int ip  = tid >> 4;          // pair 0..7
        const int iq  = tid & 15;
        const int ibA = m0 + ip;
        const int ibB = ibA + 8;
        #pragma unroll
        for (int jj = 0; jj < 8; jj++) {
            const int k = 64 * jj + 4 * iq;
            float4 h = *(const float4*)(h0 + k);
            float4 a4 = h, b4 = h;
            if (nt == 0) {                 // states[:,0,:] = s0 (pre-inject)
                *(float4*)&states[(size_t)ibA * Ll * NHID + k] = h;
                *(float4*)&states[(size_t)ibB * Ll * NHID + k] = h;
            }
            if (k < NOBS) {                // inject y_0: s + (y - s)
                float4 yA = *(const float4*)&data[((size_t)ibA * Ll) * NOBS + k];
                float4 yB = *(const float4*)&data[((size_t)ibB * Ll) * NOBS + k];
                float4 dA, dB;
                dA.x = __fsub_rn(yA.x, h.x); dA.y = __fsub_rn(yA.y, h.y);
                dA.z = __fsub_rn(yA.z, h.z); dA.w = __fsub_rn(yA.w, h.w);
                dB.x = __fsub_rn(yB.x, h.x); dB.y = __fsub_rn(yB.y, h.y);
                dB.z = __fsub_rn(yB.z, h.z); dB.w = __fsub_rn(yB.w, h.w);
                if (nt == 0) {
                    size_t oA = ((size_t)ibA * Ll) * NOBS + k;
                    size_t oB = ((size_t)ibB * Ll) * NOBS + k;
                    *(float4*)&exps[oA] = h;   *(float4*)&exps[oB] = h;
                    *(float4*)&deltas[oA]   = dA; *(float4*)&deltas[oB]   = dB;
                    *(float4*)&partials[oA] = dA; *(float4*)&partials[oB] = dB;
                }
                a4.x = __fadd_rn(h.x, dA.x); a4.y = __fadd_rn(h.y, dA.y);
                a4.z = __fadd_rn(h.z, dA.z); a4.w = __fadd_rn(h.w, dA.w);
                b4.x = __fadd_rn(h.x, dB.x); b4.y = __fadd_rn(h.y, dB.y);
                b4.z = __fadd_rn(h.z, dB.z); b4.w = __fadd_rn(h.w, dB.w);
            }
            u64* dp = &g_xpack[mt][ip][0][k];
            stcg2(dp,     pack2(a4.x, b4.x), pack2(a4.y, b4.y));
            stcg2(dp + 2, pack2(a4.z, b4.z), pack2(a4.w, b4.w));
        }
    }
    __syncthreads();                       // only CTA-wide sync in the kernel

    // lane identifiers
    const int p2 = l >> 4;                 // pair half 0/1
    const int q  = l & 15;                 // col-pair index
    const int P  = 2 * w + p2;             // this lane's pair
    const int bA = m0 + P;                 // batches bA, bA+8
    const int bB = bA + 8;
    const int nA = n0 + 2 * q;             // compute cols nA, nA+1

    for (int t = 0; t < NSTEPS; t++) {
        const u32 bt = base + (u32)t;
        const u64* xp = &g_xpack[mt][P][t & 1][0];

        // ---------- compute: 32 blocks x 8 k2, triple-buffered LDG pipeline --
        u64 acc0 = 0, acc1 = 0;            // cols nA, nA+1 (both lanes 0.0f)
        {
            ulonglong2 xa[8], xb[8], xc[8];
            if (t > 0) wait2(flagrow, bt); // chunk 0 producers (nt=0,1)
            LOADB(xa, 0);
            LOADB(xb, 1);
            #pragma unroll 1
            for (int it = 0; it < 10; it++) {
                const int b2 = 3 * it + 2;
                MW(b2);     LOADB(xc, b2);     FMAB(xa, 3 * it);
                if (b2 + 1 < 32) { MW(b2 + 1); LOADB(xa, b2 + 1); }
                FMAB(xb, 3 * it + 1);
                if (b2 + 2 < 32) { MW(b2 + 2); LOADB(xb, b2 + 2); }
                FMAB(xc, b2);
            }
            FMAB(xa, 30);
            FMAB(xb, 31);
        }

        // ---------- tanh ------------------------------------------------------
        float z0a, z0b, z1a, z1b;
        unpack2(acc0, z0a, z0b);           // (bA,nA), (bB,nA)
        unpack2(acc1, z1a, z1b);           // (bA,nA+1), (bB,nA+1)
        const float h00 = tanh_xla(z0a);
        const float h01 = tanh_xla(z0b);
        const float h10 = tanh_xla(z1a);
        const float h11 = tanh_xla(z1b);

        // ---------- states output --------------------------------------------
        float* so = states + ((size_t)t + 1) * NHID + nA;
        *(float2*)(so + (size_t)bA * Ll * NHID) = make_float2(h00, h10);
        *(float2*)(so + (size_t)bB * Ll * NHID) = make_float2(h01, h11);

        // ---------- injection + outputs for step t+1 (producer-side) ---------
        float p00 = h00, p01 = h01, p10 = h10, p11 = h11;
        if (nt == 0) {
            if (t < NSTEPS - 1) {
                float2 yA = *(const float2*)&data[((size_t)bA * Ll + t + 1) * NOBS + nA];
                float2 yB = *(const float2*)&data[((size_t)bB * Ll + t + 1) * NOBS + nA];
                float d00 = __fsub_rn(yA.x, h00);
                float d10 = __fsub_rn(yA.y, h10);
                float d01 = __fsub_rn(yB.x, h01);
                float d11 = __fsub_rn(yB.y, h11);
                size_t oA = ((size_t)bA * Ll + t + 1) * NOBS + nA;
                size_t oB = ((size_t)bB * Ll + t + 1) * NOBS + nA;
                *(float2*)&exps[oA] = make_float2(h00, h10);
                *(float2*)&exps[oB] = make_float2(h01, h11);
                *(float2*)&deltas[oA]   = make_float2(d00, d10);
                *(float2*)&deltas[oB]   = make_float2(d01, d11);
                *(float2*)&partials[oA] = make_float2(d00, d10);
                *(float2*)&partials[oB] = make_float2(d01, d11);
                p00 = __fadd_rn(h00, d00); p10 = __fadd_rn(h10, d10);
                p01 = __fadd_rn(h01, d01); p11 = __fadd_rn(h11, d11);
            } else {
                // epilogue t' = L-1: reference uses data[:, L-2] (= index t)
                float2 yA = *(const float2*)&data[((size_t)bA * Ll + t) * NOBS + nA];
                float2 yB = *(const float2*)&data[((size_t)bB * Ll + t) * NOBS + nA];
                float dAx = __fsub_rn(yA.x, h00), dAy = __fsub_rn(yA.y, h10);
                float dBx = __fsub_rn(yB.x, h01), dBy = __fsub_rn(yB.y, h11);
                size_t oA = ((size_t)bA * Ll + (Ll - 1)) * NOBS + nA;
                size_t oB = ((size_t)bB * Ll + (Ll - 1)) * NOBS + nA;
                *(float2*)&exps[oA] = make_float2(h00, h10);
                *(float2*)&exps[oB] = make_float2(h01, h11);
                *(float2*)&deltas[oA]   = make_float2(dAx, dAy);
                *(float2*)&deltas[oB]   = make_float2(dBx, dBy);
                *(float2*)&partials[oA] = make_float2(dAx, dAy);
                *(float2*)&partials[oB] = make_float2(dBx, dBy);
            }
        }

        // ---------- publish packed X for step t+1 + flag --------------------
        if (t < NSTEPS - 1) {
            stcg2(&g_xpack[mt][P][(t + 1) & 1][nA],
                  pack2(p00, p01), pack2(p10, p11));
            __syncwarp();                  // all lanes' STGs before release
            if (l == 0)
                asm volatile("red.global.release.gpu.add.u32 [%0], %1;"
                             :: "l"(myflag), "r"(1u) : "memory");
        }
    }
}

// ---------------------------------------------------------------------------
extern "C" void kernel_launch(void* const* d_in, const int* in_sizes, int n_in,
                              void* d_out, int out_size) {
    const float* data = (const float*)d_in[0];  // [128,2048,32]
    const float* A    = (const float*)d_in[1];  // [512,512]
    const float* h0   = (const float*)d_in[2];  // [1,512]
    // d_in[3] = prob (0) -> dropout identity

    float* out      = (float*)d_out;
    float* exps     = out;
    float* states   = exps   + (size_t)Bb * Ll * NOBS;
    float* deltas   = states + (size_t)Bb * Ll * NHID;
    float* partials = deltas + (size_t)Bb * Ll * NOBS;

    cudaFuncSetAttribute(ptf_persistent,
                         cudaFuncAttributeMaxDynamicSharedMemorySize, SMEM_BYTES);
    ptf_persistent<<<NCTA, NTHREADS, SMEM_BYTES>>>(data, A, h0,
                                                   exps, states, deltas, partials);
}